// round 1
// baseline (speedup 1.0000x reference)
#include <cuda_runtime.h>
#include <math.h>

#define T_TOK 4096
#define H_DIM 768
#define FF_DIM 1536
#define E_NUM 8

// ---------------- device scratch (allocation-free) ----------------
__device__ int   g_cnt[E_NUM];
__device__ int   g_tok[E_NUM * T_TOK];            // token id per (expert, slot)
__device__ float g_gate[T_TOK * 2];               // top-2 softmax gates per token
__device__ int   g_loc[T_TOK * 2];                // (expert*T + slot) per token/k
__device__ float g_hmid[(size_t)E_NUM * T_TOK * FF_DIM];   // 201 MB
__device__ float g_pout[(size_t)E_NUM * T_TOK * H_DIM];    // 100 MB

__device__ __forceinline__ float gelu_erf(float v) {
    return 0.5f * v * (1.0f + erff(v * 0.70710678118654752440f));
}

// ---------------- kernel 0: zero counters ----------------
__global__ void init_kernel() {
    if (threadIdx.x < E_NUM) g_cnt[threadIdx.x] = 0;
}

// ---------------- kernel 1: gating ----------------
// warp per token; 8 warps per block
__global__ __launch_bounds__(256) void gate_kernel(
    const float* __restrict__ x, const float* __restrict__ gw,
    float* __restrict__ logits_out)
{
    __shared__ float s_gw[E_NUM * H_DIM];  // 24 KB
    int tid = threadIdx.x;
    for (int i = tid; i < E_NUM * H_DIM; i += 256) s_gw[i] = gw[i];
    __syncthreads();

    int warp = tid >> 5, lane = tid & 31;
    int t = blockIdx.x * 8 + warp;
    const float* xr = x + (size_t)t * H_DIM;

    float acc[E_NUM];
#pragma unroll
    for (int e = 0; e < E_NUM; e++) acc[e] = 0.f;

    for (int k = lane; k < H_DIM; k += 32) {
        float xv = xr[k];
#pragma unroll
        for (int e = 0; e < E_NUM; e++)
            acc[e] = fmaf(xv, s_gw[e * H_DIM + k], acc[e]);
    }
#pragma unroll
    for (int e = 0; e < E_NUM; e++) {
#pragma unroll
        for (int o = 16; o > 0; o >>= 1)
            acc[e] += __shfl_xor_sync(0xffffffffu, acc[e], o);
    }

    if (lane == 0) {
        // top-2 (ties -> lower index, matching lax.top_k)
        int i0 = 0; float v0 = acc[0];
#pragma unroll
        for (int e = 1; e < E_NUM; e++) if (acc[e] > v0) { v0 = acc[e]; i0 = e; }
        int i1 = -1; float v1 = -3.0e38f;
#pragma unroll
        for (int e = 0; e < E_NUM; e++) if (e != i0 && acc[e] > v1) { v1 = acc[e]; i1 = e; }

        float e0 = expf(v0 - v0), e1 = expf(v1 - v0);   // e0 == 1
        float inv = 1.0f / (e0 + e1);
        float gate0 = e0 * inv, gate1 = e1 * inv;

#pragma unroll
        for (int e = 0; e < E_NUM; e++) logits_out[(size_t)t * E_NUM + e] = acc[e];

        int s0 = atomicAdd(&g_cnt[i0], 1);
        g_tok[i0 * T_TOK + s0] = t;
        g_loc[t * 2 + 0] = i0 * T_TOK + s0;
        g_gate[t * 2 + 0] = gate0;

        int s1 = atomicAdd(&g_cnt[i1], 1);
        g_tok[i1 * T_TOK + s1] = t;
        g_loc[t * 2 + 1] = i1 * T_TOK + s1;
        g_gate[t * 2 + 1] = gate1;
    }
}

// ---------------- grouped GEMM1: hmid = gelu(x_gathered @ w_fc[e]^T) ----------------
// 64x64 tile, TK=16, 256 threads, 4x4 micro-tile
#define SPAD 68
__global__ __launch_bounds__(256) void gemm1_kernel(
    const float* __restrict__ x, const float* __restrict__ wfc)
{
    int e = blockIdx.z;
    int cnt = g_cnt[e];
    int m0 = blockIdx.y * 64;
    if (m0 >= cnt) return;
    int n0 = blockIdx.x * 64;

    __shared__ float As[16][SPAD];
    __shared__ float Bs[16][SPAD];

    int tid = threadIdx.x;
    int tx = tid & 15, ty = tid >> 4;
    int lk = tid & 15, lr = tid >> 4;   // loader: kk = lk, row/col = lr + 16*p

    const float* wbase = wfc + ((size_t)e * FF_DIM + n0) * H_DIM;

    int rowtok[4];
#pragma unroll
    for (int p = 0; p < 4; p++) {
        int m = m0 + lr + p * 16;
        rowtok[p] = g_tok[e * T_TOK + (m < cnt ? m : cnt - 1)];
    }

    float acc[4][4];
#pragma unroll
    for (int i = 0; i < 4; i++)
#pragma unroll
        for (int j = 0; j < 4; j++) acc[i][j] = 0.f;

    for (int k0 = 0; k0 < H_DIM; k0 += 16) {
#pragma unroll
        for (int p = 0; p < 4; p++) {
            As[lk][lr + p * 16] = x[(size_t)rowtok[p] * H_DIM + k0 + lk];
            Bs[lk][lr + p * 16] = wbase[(size_t)(lr + p * 16) * H_DIM + k0 + lk];
        }
        __syncthreads();
#pragma unroll
        for (int kk = 0; kk < 16; kk++) {
            float4 a = *(const float4*)&As[kk][ty * 4];
            float4 b = *(const float4*)&Bs[kk][tx * 4];
            acc[0][0] = fmaf(a.x, b.x, acc[0][0]); acc[0][1] = fmaf(a.x, b.y, acc[0][1]);
            acc[0][2] = fmaf(a.x, b.z, acc[0][2]); acc[0][3] = fmaf(a.x, b.w, acc[0][3]);
            acc[1][0] = fmaf(a.y, b.x, acc[1][0]); acc[1][1] = fmaf(a.y, b.y, acc[1][1]);
            acc[1][2] = fmaf(a.y, b.z, acc[1][2]); acc[1][3] = fmaf(a.y, b.w, acc[1][3]);
            acc[2][0] = fmaf(a.z, b.x, acc[2][0]); acc[2][1] = fmaf(a.z, b.y, acc[2][1]);
            acc[2][2] = fmaf(a.z, b.z, acc[2][2]); acc[2][3] = fmaf(a.z, b.w, acc[2][3]);
            acc[3][0] = fmaf(a.w, b.x, acc[3][0]); acc[3][1] = fmaf(a.w, b.y, acc[3][1]);
            acc[3][2] = fmaf(a.w, b.z, acc[3][2]); acc[3][3] = fmaf(a.w, b.w, acc[3][3]);
        }
        __syncthreads();
    }

#pragma unroll
    for (int i = 0; i < 4; i++) {
        int m = m0 + ty * 4 + i;
        if (m < cnt) {
            float4 v;
            v.x = gelu_erf(acc[i][0]); v.y = gelu_erf(acc[i][1]);
            v.z = gelu_erf(acc[i][2]); v.w = gelu_erf(acc[i][3]);
            *(float4*)&g_hmid[((size_t)(e * T_TOK + m)) * FF_DIM + n0 + tx * 4] = v;
        }
    }
}

// ---------------- grouped GEMM2: pout = hmid @ w_proj[e]^T ----------------
__global__ __launch_bounds__(256) void gemm2_kernel(const float* __restrict__ wproj)
{
    int e = blockIdx.z;
    int cnt = g_cnt[e];
    int m0 = blockIdx.y * 64;
    if (m0 >= cnt) return;
    int n0 = blockIdx.x * 64;

    __shared__ float As[16][SPAD];
    __shared__ float Bs[16][SPAD];

    int tid = threadIdx.x;
    int tx = tid & 15, ty = tid >> 4;
    int lk = tid & 15, lr = tid >> 4;

    const float* abase = &g_hmid[((size_t)(e * T_TOK + m0)) * FF_DIM];
    const float* wbase = wproj + ((size_t)e * H_DIM + n0) * FF_DIM;

    float acc[4][4];
#pragma unroll
    for (int i = 0; i < 4; i++)
#pragma unroll
        for (int j = 0; j < 4; j++) acc[i][j] = 0.f;

    for (int k0 = 0; k0 < FF_DIM; k0 += 16) {
#pragma unroll
        for (int p = 0; p < 4; p++) {
            As[lk][lr + p * 16] = abase[(size_t)(lr + p * 16) * FF_DIM + k0 + lk];
            Bs[lk][lr + p * 16] = wbase[(size_t)(lr + p * 16) * FF_DIM + k0 + lk];
        }
        __syncthreads();
#pragma unroll
        for (int kk = 0; kk < 16; kk++) {
            float4 a = *(const float4*)&As[kk][ty * 4];
            float4 b = *(const float4*)&Bs[kk][tx * 4];
            acc[0][0] = fmaf(a.x, b.x, acc[0][0]); acc[0][1] = fmaf(a.x, b.y, acc[0][1]);
            acc[0][2] = fmaf(a.x, b.z, acc[0][2]); acc[0][3] = fmaf(a.x, b.w, acc[0][3]);
            acc[1][0] = fmaf(a.y, b.x, acc[1][0]); acc[1][1] = fmaf(a.y, b.y, acc[1][1]);
            acc[1][2] = fmaf(a.y, b.z, acc[1][2]); acc[1][3] = fmaf(a.y, b.w, acc[1][3]);
            acc[2][0] = fmaf(a.z, b.x, acc[2][0]); acc[2][1] = fmaf(a.z, b.y, acc[2][1]);
            acc[2][2] = fmaf(a.z, b.z, acc[2][2]); acc[2][3] = fmaf(a.z, b.w, acc[2][3]);
            acc[3][0] = fmaf(a.w, b.x, acc[3][0]); acc[3][1] = fmaf(a.w, b.y, acc[3][1]);
            acc[3][2] = fmaf(a.w, b.z, acc[3][2]); acc[3][3] = fmaf(a.w, b.w, acc[3][3]);
        }
        __syncthreads();
    }

#pragma unroll
    for (int i = 0; i < 4; i++) {
        int m = m0 + ty * 4 + i;
        if (m < cnt) {
            float4 v = make_float4(acc[i][0], acc[i][1], acc[i][2], acc[i][3]);
            *(float4*)&g_pout[((size_t)(e * T_TOK + m)) * H_DIM + n0 + tx * 4] = v;
        }
    }
}

// ---------------- kernel 4: combine (deterministic, no atomics) ----------------
__global__ __launch_bounds__(256) void combine_kernel(float* __restrict__ out)
{
    int i = blockIdx.x * 256 + threadIdx.x;     // over T*H/4
    int t = i / (H_DIM / 4);
    int h4 = i - t * (H_DIM / 4);
    float g0 = g_gate[t * 2 + 0], g1 = g_gate[t * 2 + 1];
    int l0 = g_loc[t * 2 + 0], l1 = g_loc[t * 2 + 1];
    float4 a = *(const float4*)&g_pout[(size_t)l0 * H_DIM + h4 * 4];
    float4 b = *(const float4*)&g_pout[(size_t)l1 * H_DIM + h4 * 4];
    float4 r;
    r.x = g0 * a.x + g1 * b.x;
    r.y = g0 * a.y + g1 * b.y;
    r.z = g0 * a.z + g1 * b.z;
    r.w = g0 * a.w + g1 * b.w;
    *(float4*)&out[(size_t)t * H_DIM + h4 * 4] = r;
}

// ---------------- launch ----------------
extern "C" void kernel_launch(void* const* d_in, const int* in_sizes, int n_in,
                              void* d_out, int out_size)
{
    const float* x     = (const float*)d_in[0];   // [T, H]
    const float* gw    = (const float*)d_in[1];   // [E, H]
    const float* wfc   = (const float*)d_in[2];   // [E, FF, H]
    const float* wproj = (const float*)d_in[3];   // [E, H, FF]
    float* out    = (float*)d_out;                        // [T, H]
    float* logits = (float*)d_out + (size_t)T_TOK * H_DIM; // [T, E]

    init_kernel<<<1, 32>>>();
    gate_kernel<<<T_TOK / 8, 256>>>(x, gw, logits);

    dim3 g1(FF_DIM / 64, T_TOK / 64, E_NUM);
    gemm1_kernel<<<g1, 256>>>(x, wfc);

    dim3 g2(H_DIM / 64, T_TOK / 64, E_NUM);
    gemm2_kernel<<<g2, 256>>>(wproj);

    combine_kernel<<<(T_TOK * H_DIM / 4) / 256, 256>>>(out);
}

// round 3
// speedup vs baseline: 5.1974x; 5.1974x over previous
#include <cuda_runtime.h>
#include <cuda_fp16.h>
#include <cstdint>
#include <math.h>

#define T_TOK 4096
#define H_DIM 768
#define FF_DIM 1536
#define E_NUM 8

// ---------------- device scratch (allocation-free) ----------------
__device__ int   g_cnt[E_NUM];
__device__ int   g_tok[E_NUM * T_TOK];
__device__ float g_gate[T_TOK * 2];
__device__ int   g_loc[T_TOK * 2];
__device__ __half g_xh[(size_t)T_TOK * H_DIM];
__device__ __half g_wfch[(size_t)E_NUM * FF_DIM * H_DIM];
__device__ __half g_wprojh[(size_t)E_NUM * H_DIM * FF_DIM];
__device__ __half g_hmidh[(size_t)E_NUM * T_TOK * FF_DIM];
__device__ float  g_pout[(size_t)E_NUM * T_TOK * H_DIM];

__device__ __forceinline__ uint32_t smem_to_u32(const void* p) {
    uint32_t a;
    asm("{ .reg .u64 t; cvta.to.shared.u64 t, %1; cvt.u32.u64 %0, t; }" : "=r"(a) : "l"(p));
    return a;
}
__device__ __forceinline__ void ldsm_x4(uint32_t& r0, uint32_t& r1, uint32_t& r2, uint32_t& r3,
                                        uint32_t addr) {
    asm volatile("ldmatrix.sync.aligned.m8n8.x4.shared.b16 {%0,%1,%2,%3}, [%4];"
                 : "=r"(r0), "=r"(r1), "=r"(r2), "=r"(r3) : "r"(addr));
}
__device__ __forceinline__ void mma16816(float* d, const uint32_t* a, uint32_t b0, uint32_t b1) {
    asm volatile("mma.sync.aligned.m16n8k16.row.col.f32.f16.f16.f32 "
                 "{%0,%1,%2,%3}, {%4,%5,%6,%7}, {%8,%9}, {%0,%1,%2,%3};"
                 : "+f"(d[0]), "+f"(d[1]), "+f"(d[2]), "+f"(d[3])
                 : "r"(a[0]), "r"(a[1]), "r"(a[2]), "r"(a[3]), "r"(b0), "r"(b1));
}
#define CP_ASYNC16(smem_u32, gptr) \
    asm volatile("cp.async.cg.shared.global [%0], [%1], 16;" :: "r"(smem_u32), "l"(gptr))
#define CP_COMMIT() asm volatile("cp.async.commit_group;")
#define CP_WAIT1()  asm volatile("cp.async.wait_group 1;")
#define CP_WAIT0()  asm volatile("cp.async.wait_group 0;")

__device__ __forceinline__ float gelu_erf(float v) {
    return 0.5f * v * (1.0f + erff(v * 0.70710678118654752440f));
}

// ---------------- init ----------------
__global__ void init_kernel() {
    if (threadIdx.x < E_NUM) g_cnt[threadIdx.x] = 0;
}

// ---------------- gating ----------------
__global__ __launch_bounds__(256) void gate_kernel(
    const float* __restrict__ x, const float* __restrict__ gw,
    float* __restrict__ logits_out)
{
    __shared__ float s_gw[E_NUM * H_DIM];
    int tid = threadIdx.x;
    for (int i = tid; i < E_NUM * H_DIM; i += 256) s_gw[i] = gw[i];
    __syncthreads();

    int warp = tid >> 5, lane = tid & 31;
    int t = blockIdx.x * 8 + warp;
    const float* xr = x + (size_t)t * H_DIM;

    float acc[E_NUM];
#pragma unroll
    for (int e = 0; e < E_NUM; e++) acc[e] = 0.f;
    for (int k = lane; k < H_DIM; k += 32) {
        float xv = xr[k];
#pragma unroll
        for (int e = 0; e < E_NUM; e++)
            acc[e] = fmaf(xv, s_gw[e * H_DIM + k], acc[e]);
    }
#pragma unroll
    for (int e = 0; e < E_NUM; e++) {
#pragma unroll
        for (int o = 16; o > 0; o >>= 1)
            acc[e] += __shfl_xor_sync(0xffffffffu, acc[e], o);
    }

    if (lane == 0) {
        int i0 = 0; float v0 = acc[0];
#pragma unroll
        for (int e = 1; e < E_NUM; e++) if (acc[e] > v0) { v0 = acc[e]; i0 = e; }
        int i1 = -1; float v1 = -3.0e38f;
#pragma unroll
        for (int e = 0; e < E_NUM; e++) if (e != i0 && acc[e] > v1) { v1 = acc[e]; i1 = e; }

        float e1 = expf(v1 - v0);
        float inv = 1.0f / (1.0f + e1);

#pragma unroll
        for (int e = 0; e < E_NUM; e++) logits_out[(size_t)t * E_NUM + e] = acc[e];

        int s0 = atomicAdd(&g_cnt[i0], 1);
        g_tok[i0 * T_TOK + s0] = t;
        g_loc[t * 2 + 0] = i0 * T_TOK + s0;
        g_gate[t * 2 + 0] = inv;
        int s1 = atomicAdd(&g_cnt[i1], 1);
        g_tok[i1 * T_TOK + s1] = t;
        g_loc[t * 2 + 1] = i1 * T_TOK + s1;
        g_gate[t * 2 + 1] = e1 * inv;
    }
}

// ---------------- fp32 -> fp16 conversion (4 elems / thread) ----------------
__global__ __launch_bounds__(256) void cvt_fp16_kernel(
    const float4* __restrict__ src, uint2* __restrict__ dst)
{
    size_t i = (size_t)blockIdx.x * 256 + threadIdx.x;
    float4 v = src[i];
    __half2 a = __floats2half2_rn(v.x, v.y);
    __half2 b = __floats2half2_rn(v.z, v.w);
    uint2 u;
    u.x = *(uint32_t*)&a;
    u.y = *(uint32_t*)&b;
    dst[i] = u;
}

// ---------------- GEMM tile machinery ----------------
// smem: A0 16K | B0 16K | A1 16K | B1 16K
#define SM_A0 0
#define SM_B0 16384
#define SM_A1 32768
#define SM_B1 49152
#define SMEM_BYTES 65536

#define LOAD_CHUNK(c, abase, bbase) do {                                        \
    _Pragma("unroll")                                                           \
    for (int j = 0; j < 4; j++) {                                               \
        int grp = lc4 + j;                                                      \
        uint32_t soff = (uint32_t)(lrow * 128 + ((grp ^ (lrow & 7)) << 4));     \
        CP_ASYNC16((abase) + soff, aptr + (size_t)(c) * 64 + grp * 8);          \
        CP_ASYNC16((bbase) + soff, bptr + (size_t)(c) * 64 + grp * 8);          \
    }                                                                           \
} while (0)

#define COMPUTE_CHUNK(abase, bbase) do {                                        \
    _Pragma("unroll")                                                           \
    for (int kk8 = 0; kk8 < 8; kk8 += 2) {                                      \
        uint32_t af[4][4], bf[2][4];                                            \
        _Pragma("unroll")                                                       \
        for (int i = 0; i < 4; i++) {                                           \
            uint32_t ad = (abase) + (uint32_t)((wm + 16 * i + arow) * 128)      \
                        + (uint32_t)((((kk8 + asub) ^ l7)) << 4);               \
            ldsm_x4(af[i][0], af[i][1], af[i][2], af[i][3], ad);                \
        }                                                                       \
        _Pragma("unroll")                                                       \
        for (int j2 = 0; j2 < 2; j2++) {                                        \
            uint32_t bd = (bbase) + (uint32_t)((wn + 16 * j2 + brow) * 128)     \
                        + (uint32_t)((((kk8 + bsub) ^ l7)) << 4);               \
            ldsm_x4(bf[j2][0], bf[j2][1], bf[j2][2], bf[j2][3], bd);            \
        }                                                                       \
        _Pragma("unroll")                                                       \
        for (int i = 0; i < 4; i++)                                             \
            _Pragma("unroll")                                                   \
            for (int j = 0; j < 4; j++)                                         \
                mma16816(acc[i][j], af[i], bf[j >> 1][(j & 1) * 2],             \
                         bf[j >> 1][(j & 1) * 2 + 1]);                          \
    }                                                                           \
} while (0)

// ---------------- GEMM1: hmid = gelu(x_gather @ wfc^T) -> fp16 ----------------
__global__ __launch_bounds__(256) void moe_gemm1_kernel()
{
    int e = blockIdx.z;
    int cnt = g_cnt[e];
    int m0 = blockIdx.y * 128;
    if (m0 >= cnt) return;
    int n0 = blockIdx.x * 128;

    extern __shared__ char smem[];
    uint32_t sb = smem_to_u32(smem);
    int tid = threadIdx.x, wid = tid >> 5, lane = tid & 31;
    int sub = lane >> 3, l7 = lane & 7;
    int wm = (wid >> 2) * 64, wn = (wid & 3) * 32;
    int arow = l7 + ((sub & 1) << 3), asub = sub >> 1;
    int brow = l7 + ((sub >> 1) << 3), bsub = sub & 1;

    int lrow = tid >> 1;            // 0..127
    int lc4 = (tid & 1) * 4;        // 0 or 4

    int am = m0 + lrow; if (am >= cnt) am = cnt - 1;
    int atok = g_tok[e * T_TOK + am];
    const __half* aptr = g_xh + (size_t)atok * H_DIM;
    const __half* bptr = g_wfch + ((size_t)e * FF_DIM + n0 + lrow) * H_DIM;

    float acc[4][4][4];
#pragma unroll
    for (int i = 0; i < 4; i++)
#pragma unroll
        for (int j = 0; j < 4; j++)
#pragma unroll
            for (int q = 0; q < 4; q++) acc[i][j][q] = 0.f;

    const int NC = H_DIM / 64;      // 12
    LOAD_CHUNK(0, sb + SM_A0, sb + SM_B0);
    CP_COMMIT();
    int buf = 0;
    for (int c = 0; c < NC; c++) {
        if (c + 1 < NC) {
            if (buf == 0) LOAD_CHUNK(c + 1, sb + SM_A1, sb + SM_B1);
            else          LOAD_CHUNK(c + 1, sb + SM_A0, sb + SM_B0);
            CP_COMMIT();
            CP_WAIT1();
        } else {
            CP_WAIT0();
        }
        __syncthreads();
        if (buf == 0) COMPUTE_CHUNK(sb + SM_A0, sb + SM_B0);
        else          COMPUTE_CHUNK(sb + SM_A1, sb + SM_B1);
        __syncthreads();
        buf ^= 1;
    }

    // epilogue: gelu -> fp16
    int ml = lane >> 2;             // 0..7
    int cl = (lane & 3) * 2;
#pragma unroll
    for (int i = 0; i < 4; i++) {
        int r0 = m0 + wm + 16 * i + ml;
        int r1 = r0 + 8;
#pragma unroll
        for (int j = 0; j < 4; j++) {
            int col = n0 + wn + 8 * j + cl;
            if (r0 < cnt) {
                __half2 h = __floats2half2_rn(gelu_erf(acc[i][j][0]), gelu_erf(acc[i][j][1]));
                *(__half2*)&g_hmidh[((size_t)e * T_TOK + r0) * FF_DIM + col] = h;
            }
            if (r1 < cnt) {
                __half2 h = __floats2half2_rn(gelu_erf(acc[i][j][2]), gelu_erf(acc[i][j][3]));
                *(__half2*)&g_hmidh[((size_t)e * T_TOK + r1) * FF_DIM + col] = h;
            }
        }
    }
}

// ---------------- GEMM2: pout = hmid @ wproj^T -> fp32 ----------------
__global__ __launch_bounds__(256) void moe_gemm2_kernel()
{
    int e = blockIdx.z;
    int cnt = g_cnt[e];
    int m0 = blockIdx.y * 128;
    if (m0 >= cnt) return;
    int n0 = blockIdx.x * 128;

    extern __shared__ char smem[];
    uint32_t sb = smem_to_u32(smem);
    int tid = threadIdx.x, wid = tid >> 5, lane = tid & 31;
    int sub = lane >> 3, l7 = lane & 7;
    int wm = (wid >> 2) * 64, wn = (wid & 3) * 32;
    int arow = l7 + ((sub & 1) << 3), asub = sub >> 1;
    int brow = l7 + ((sub >> 1) << 3), bsub = sub & 1;

    int lrow = tid >> 1;
    int lc4 = (tid & 1) * 4;

    int am = m0 + lrow; if (am >= cnt) am = cnt - 1;
    const __half* aptr = g_hmidh + ((size_t)e * T_TOK + am) * FF_DIM;
    const __half* bptr = g_wprojh + ((size_t)e * H_DIM + n0 + lrow) * FF_DIM;

    float acc[4][4][4];
#pragma unroll
    for (int i = 0; i < 4; i++)
#pragma unroll
        for (int j = 0; j < 4; j++)
#pragma unroll
            for (int q = 0; q < 4; q++) acc[i][j][q] = 0.f;

    const int NC = FF_DIM / 64;     // 24
    LOAD_CHUNK(0, sb + SM_A0, sb + SM_B0);
    CP_COMMIT();
    int buf = 0;
    for (int c = 0; c < NC; c++) {
        if (c + 1 < NC) {
            if (buf == 0) LOAD_CHUNK(c + 1, sb + SM_A1, sb + SM_B1);
            else          LOAD_CHUNK(c + 1, sb + SM_A0, sb + SM_B0);
            CP_COMMIT();
            CP_WAIT1();
        } else {
            CP_WAIT0();
        }
        __syncthreads();
        if (buf == 0) COMPUTE_CHUNK(sb + SM_A0, sb + SM_B0);
        else          COMPUTE_CHUNK(sb + SM_A1, sb + SM_B1);
        __syncthreads();
        buf ^= 1;
    }

    int ml = lane >> 2;
    int cl = (lane & 3) * 2;
#pragma unroll
    for (int i = 0; i < 4; i++) {
        int r0 = m0 + wm + 16 * i + ml;
        int r1 = r0 + 8;
#pragma unroll
        for (int j = 0; j < 4; j++) {
            int col = n0 + wn + 8 * j + cl;
            if (r0 < cnt) {
                float2 v = make_float2(acc[i][j][0], acc[i][j][1]);
                *(float2*)&g_pout[((size_t)e * T_TOK + r0) * H_DIM + col] = v;
            }
            if (r1 < cnt) {
                float2 v = make_float2(acc[i][j][2], acc[i][j][3]);
                *(float2*)&g_pout[((size_t)e * T_TOK + r1) * H_DIM + col] = v;
            }
        }
    }
}

// ---------------- combine ----------------
__global__ __launch_bounds__(256) void combine_kernel(float* __restrict__ out)
{
    int i = blockIdx.x * 256 + threadIdx.x;
    int t = i / (H_DIM / 4);
    int h4 = i - t * (H_DIM / 4);
    float g0 = g_gate[t * 2 + 0], g1 = g_gate[t * 2 + 1];
    int l0 = g_loc[t * 2 + 0], l1 = g_loc[t * 2 + 1];
    float4 a = *(const float4*)&g_pout[(size_t)l0 * H_DIM + h4 * 4];
    float4 b = *(const float4*)&g_pout[(size_t)l1 * H_DIM + h4 * 4];
    float4 r;
    r.x = g0 * a.x + g1 * b.x;
    r.y = g0 * a.y + g1 * b.y;
    r.z = g0 * a.z + g1 * b.z;
    r.w = g0 * a.w + g1 * b.w;
    *(float4*)&out[(size_t)t * H_DIM + h4 * 4] = r;
}

// ---------------- launch ----------------
extern "C" void kernel_launch(void* const* d_in, const int* in_sizes, int n_in,
                              void* d_out, int out_size)
{
    const float* x     = (const float*)d_in[0];
    const float* gw    = (const float*)d_in[1];
    const float* wfc   = (const float*)d_in[2];
    const float* wproj = (const float*)d_in[3];
    float* out    = (float*)d_out;
    float* logits = (float*)d_out + (size_t)T_TOK * H_DIM;

    cudaFuncSetAttribute(moe_gemm1_kernel, cudaFuncAttributeMaxDynamicSharedMemorySize, SMEM_BYTES);
    cudaFuncSetAttribute(moe_gemm2_kernel, cudaFuncAttributeMaxDynamicSharedMemorySize, SMEM_BYTES);

    __half* xh;     cudaGetSymbolAddress((void**)&xh, g_xh);
    __half* wfch;   cudaGetSymbolAddress((void**)&wfch, g_wfch);
    __half* wprojh; cudaGetSymbolAddress((void**)&wprojh, g_wprojh);

    init_kernel<<<1, 32>>>();
    gate_kernel<<<T_TOK / 8, 256>>>(x, gw, logits);

    cvt_fp16_kernel<<<(T_TOK * H_DIM / 4) / 256, 256>>>((const float4*)x, (uint2*)xh);
    cvt_fp16_kernel<<<((size_t)E_NUM * FF_DIM * H_DIM / 4) / 256, 256>>>((const float4*)wfc, (uint2*)wfch);
    cvt_fp16_kernel<<<((size_t)E_NUM * H_DIM * FF_DIM / 4) / 256, 256>>>((const float4*)wproj, (uint2*)wprojh);

    dim3 g1(FF_DIM / 128, T_TOK / 128, E_NUM);
    moe_gemm1_kernel<<<g1, 256, SMEM_BYTES>>>();
    dim3 g2(H_DIM / 128, T_TOK / 128, E_NUM);
    moe_gemm2_kernel<<<g2, 256, SMEM_BYTES>>>();

    combine_kernel<<<(T_TOK * H_DIM / 4) / 256, 256>>>(out);
}

// round 4
// speedup vs baseline: 5.3420x; 1.0278x over previous
#include <cuda_runtime.h>
#include <cuda_fp16.h>
#include <cstdint>
#include <math.h>

#define T_TOK 4096
#define H_DIM 768
#define FF_DIM 1536
#define E_NUM 8

// ---------------- device scratch (allocation-free) ----------------
__device__ int   g_cnt[E_NUM];
__device__ int   g_tok[E_NUM * T_TOK];
__device__ float g_gate[T_TOK * 2];
__device__ int   g_loc[T_TOK * 2];
__device__ __half g_xh[(size_t)T_TOK * H_DIM];
__device__ __half g_wfch[(size_t)E_NUM * FF_DIM * H_DIM];
__device__ __half g_wprojh[(size_t)E_NUM * H_DIM * FF_DIM];
__device__ __half g_hmidh[(size_t)E_NUM * T_TOK * FF_DIM];
__device__ float  g_pout[(size_t)E_NUM * T_TOK * H_DIM];

__device__ __forceinline__ uint32_t smem_to_u32(const void* p) {
    uint32_t a;
    asm("{ .reg .u64 t; cvta.to.shared.u64 t, %1; cvt.u32.u64 %0, t; }" : "=r"(a) : "l"(p));
    return a;
}
__device__ __forceinline__ void ldsm_x4(uint32_t& r0, uint32_t& r1, uint32_t& r2, uint32_t& r3,
                                        uint32_t addr) {
    asm volatile("ldmatrix.sync.aligned.m8n8.x4.shared.b16 {%0,%1,%2,%3}, [%4];"
                 : "=r"(r0), "=r"(r1), "=r"(r2), "=r"(r3) : "r"(addr));
}
__device__ __forceinline__ void mma16816(float* d, const uint32_t* a, uint32_t b0, uint32_t b1) {
    asm volatile("mma.sync.aligned.m16n8k16.row.col.f32.f16.f16.f32 "
                 "{%0,%1,%2,%3}, {%4,%5,%6,%7}, {%8,%9}, {%0,%1,%2,%3};"
                 : "+f"(d[0]), "+f"(d[1]), "+f"(d[2]), "+f"(d[3])
                 : "r"(a[0]), "r"(a[1]), "r"(a[2]), "r"(a[3]), "r"(b0), "r"(b1));
}
#define CP_ASYNC16(smem_u32, gptr) \
    asm volatile("cp.async.cg.shared.global [%0], [%1], 16;" :: "r"(smem_u32), "l"(gptr))
#define CP_COMMIT() asm volatile("cp.async.commit_group;")
#define CP_WAIT1()  asm volatile("cp.async.wait_group 1;")

__device__ __forceinline__ float gelu_erf(float v) {
    return 0.5f * v * (1.0f + erff(v * 0.70710678118654752440f));
}

// ---------------- init ----------------
__global__ void init_kernel() {
    if (threadIdx.x < E_NUM) g_cnt[threadIdx.x] = 0;
}

// ---------------- gating ----------------
__global__ __launch_bounds__(256) void gate_kernel(
    const float* __restrict__ x, const float* __restrict__ gw,
    float* __restrict__ logits_out)
{
    __shared__ float s_gw[E_NUM * H_DIM];
    int tid = threadIdx.x;
    for (int i = tid; i < E_NUM * H_DIM; i += 256) s_gw[i] = gw[i];
    __syncthreads();

    int warp = tid >> 5, lane = tid & 31;
    int t = blockIdx.x * 8 + warp;
    const float* xr = x + (size_t)t * H_DIM;

    float acc[E_NUM];
#pragma unroll
    for (int e = 0; e < E_NUM; e++) acc[e] = 0.f;
    for (int k = lane; k < H_DIM; k += 32) {
        float xv = xr[k];
#pragma unroll
        for (int e = 0; e < E_NUM; e++)
            acc[e] = fmaf(xv, s_gw[e * H_DIM + k], acc[e]);
    }
#pragma unroll
    for (int e = 0; e < E_NUM; e++) {
#pragma unroll
        for (int o = 16; o > 0; o >>= 1)
            acc[e] += __shfl_xor_sync(0xffffffffu, acc[e], o);
    }

    if (lane == 0) {
        int i0 = 0; float v0 = acc[0];
#pragma unroll
        for (int e = 1; e < E_NUM; e++) if (acc[e] > v0) { v0 = acc[e]; i0 = e; }
        int i1 = -1; float v1 = -3.0e38f;
#pragma unroll
        for (int e = 0; e < E_NUM; e++) if (e != i0 && acc[e] > v1) { v1 = acc[e]; i1 = e; }

        float e1 = expf(v1 - v0);
        float inv = 1.0f / (1.0f + e1);

#pragma unroll
        for (int e = 0; e < E_NUM; e++) logits_out[(size_t)t * E_NUM + e] = acc[e];

        int s0 = atomicAdd(&g_cnt[i0], 1);
        g_tok[i0 * T_TOK + s0] = t;
        g_loc[t * 2 + 0] = i0 * T_TOK + s0;
        g_gate[t * 2 + 0] = inv;
        int s1 = atomicAdd(&g_cnt[i1], 1);
        g_tok[i1 * T_TOK + s1] = t;
        g_loc[t * 2 + 1] = i1 * T_TOK + s1;
        g_gate[t * 2 + 1] = e1 * inv;
    }
}

// ---------------- fp32 -> fp16 conversion (8 elems / thread) ----------------
__global__ __launch_bounds__(256) void cvt_fp16_kernel(
    const float4* __restrict__ src, uint4* __restrict__ dst)
{
    size_t i = (size_t)blockIdx.x * 256 + threadIdx.x;
    float4 v0 = src[i * 2];
    float4 v1 = src[i * 2 + 1];
    __half2 a = __floats2half2_rn(v0.x, v0.y);
    __half2 b = __floats2half2_rn(v0.z, v0.w);
    __half2 c = __floats2half2_rn(v1.x, v1.y);
    __half2 d = __floats2half2_rn(v1.z, v1.w);
    uint4 u;
    u.x = *(uint32_t*)&a; u.y = *(uint32_t*)&b;
    u.z = *(uint32_t*)&c; u.w = *(uint32_t*)&d;
    dst[i] = u;
}

// ---------------- GEMM tile machinery ----------------
// 3 stages x (A 16K | B 16K) = 96KB
#define NSTAGE 3
#define STG_STRIDE 32768
#define SMEM_BYTES (NSTAGE * STG_STRIDE)

#define LOAD_CHUNK(c, stg) do {                                                 \
    uint32_t ab = sb + (stg) * STG_STRIDE;                                      \
    uint32_t bb = ab + 16384;                                                   \
    _Pragma("unroll")                                                           \
    for (int j = 0; j < 4; j++) {                                               \
        int grp = lc4 + j;                                                      \
        uint32_t soff = (uint32_t)(lrow * 128 + ((grp ^ (lrow & 7)) << 4));     \
        CP_ASYNC16(ab + soff, aptr + (size_t)(c) * 64 + grp * 8);               \
        CP_ASYNC16(bb + soff, bptr + (size_t)(c) * 64 + grp * 8);               \
    }                                                                           \
} while (0)

#define COMPUTE_CHUNK(stg) do {                                                 \
    uint32_t ab = sb + (stg) * STG_STRIDE;                                      \
    uint32_t bb = ab + 16384;                                                   \
    _Pragma("unroll")                                                           \
    for (int kk8 = 0; kk8 < 8; kk8 += 2) {                                      \
        uint32_t af[4][4], bf[2][4];                                            \
        _Pragma("unroll")                                                       \
        for (int i = 0; i < 4; i++) {                                           \
            uint32_t ad = ab + (uint32_t)((wm + 16 * i + arow) * 128)           \
                        + (uint32_t)((((kk8 + asub) ^ l7)) << 4);               \
            ldsm_x4(af[i][0], af[i][1], af[i][2], af[i][3], ad);                \
        }                                                                       \
        _Pragma("unroll")                                                       \
        for (int j2 = 0; j2 < 2; j2++) {                                        \
            uint32_t bd = bb + (uint32_t)((wn + 16 * j2 + brow) * 128)          \
                        + (uint32_t)((((kk8 + bsub) ^ l7)) << 4);               \
            ldsm_x4(bf[j2][0], bf[j2][1], bf[j2][2], bf[j2][3], bd);            \
        }                                                                       \
        _Pragma("unroll")                                                       \
        for (int i = 0; i < 4; i++)                                             \
            _Pragma("unroll")                                                   \
            for (int j = 0; j < 4; j++)                                         \
                mma16816(acc[i][j], af[i], bf[j >> 1][(j & 1) * 2],             \
                         bf[j >> 1][(j & 1) * 2 + 1]);                          \
    }                                                                           \
} while (0)

// Single-sync 3-stage mainloop
#define MAINLOOP(NC) do {                                                       \
    LOAD_CHUNK(0, 0); CP_COMMIT();                                              \
    LOAD_CHUNK(1, 1); CP_COMMIT();                                              \
    int cstg = 0, lstg = 2;                                                     \
    for (int c = 0; c < (NC); c++) {                                            \
        CP_WAIT1();                                                             \
        __syncthreads();                                                        \
        if (c + 2 < (NC)) LOAD_CHUNK(c + 2, lstg);                              \
        CP_COMMIT();                                                            \
        COMPUTE_CHUNK(cstg);                                                    \
        lstg = cstg;                                                            \
        cstg = (cstg + 1 == NSTAGE) ? 0 : cstg + 1;                             \
    }                                                                           \
} while (0)

// ---------------- GEMM1: hmid = gelu(x_gather @ wfc^T) -> fp16 ----------------
__global__ __launch_bounds__(256, 2) void moe_gemm1_kernel()
{
    int e = blockIdx.z;
    int cnt = g_cnt[e];
    int m0 = blockIdx.y * 128;
    if (m0 >= cnt) return;
    int n0 = blockIdx.x * 128;

    extern __shared__ char smem[];
    uint32_t sb = smem_to_u32(smem);
    int tid = threadIdx.x, wid = tid >> 5, lane = tid & 31;
    int sub = lane >> 3, l7 = lane & 7;
    int wm = (wid >> 2) * 64, wn = (wid & 3) * 32;
    int arow = l7 + ((sub & 1) << 3), asub = sub >> 1;
    int brow = l7 + ((sub >> 1) << 3), bsub = sub & 1;

    int lrow = tid >> 1;            // 0..127
    int lc4 = (tid & 1) * 4;        // 0 or 4

    int am = m0 + lrow; if (am >= cnt) am = cnt - 1;
    int atok = g_tok[e * T_TOK + am];
    const __half* aptr = g_xh + (size_t)atok * H_DIM;
    const __half* bptr = g_wfch + ((size_t)e * FF_DIM + n0 + lrow) * H_DIM;

    float acc[4][4][4];
#pragma unroll
    for (int i = 0; i < 4; i++)
#pragma unroll
        for (int j = 0; j < 4; j++)
#pragma unroll
            for (int q = 0; q < 4; q++) acc[i][j][q] = 0.f;

    MAINLOOP(H_DIM / 64);

    // epilogue: gelu -> fp16
    int ml = lane >> 2;             // 0..7
    int cl = (lane & 3) * 2;
#pragma unroll
    for (int i = 0; i < 4; i++) {
        int r0 = m0 + wm + 16 * i + ml;
        int r1 = r0 + 8;
#pragma unroll
        for (int j = 0; j < 4; j++) {
            int col = n0 + wn + 8 * j + cl;
            if (r0 < cnt) {
                __half2 h = __floats2half2_rn(gelu_erf(acc[i][j][0]), gelu_erf(acc[i][j][1]));
                *(__half2*)&g_hmidh[((size_t)e * T_TOK + r0) * FF_DIM + col] = h;
            }
            if (r1 < cnt) {
                __half2 h = __floats2half2_rn(gelu_erf(acc[i][j][2]), gelu_erf(acc[i][j][3]));
                *(__half2*)&g_hmidh[((size_t)e * T_TOK + r1) * FF_DIM + col] = h;
            }
        }
    }
}

// ---------------- GEMM2: pout = hmid @ wproj^T -> fp32 ----------------
__global__ __launch_bounds__(256, 2) void moe_gemm2_kernel()
{
    int e = blockIdx.z;
    int cnt = g_cnt[e];
    int m0 = blockIdx.y * 128;
    if (m0 >= cnt) return;
    int n0 = blockIdx.x * 128;

    extern __shared__ char smem[];
    uint32_t sb = smem_to_u32(smem);
    int tid = threadIdx.x, wid = tid >> 5, lane = tid & 31;
    int sub = lane >> 3, l7 = lane & 7;
    int wm = (wid >> 2) * 64, wn = (wid & 3) * 32;
    int arow = l7 + ((sub & 1) << 3), asub = sub >> 1;
    int brow = l7 + ((sub >> 1) << 3), bsub = sub & 1;

    int lrow = tid >> 1;
    int lc4 = (tid & 1) * 4;

    int am = m0 + lrow; if (am >= cnt) am = cnt - 1;
    const __half* aptr = g_hmidh + ((size_t)e * T_TOK + am) * FF_DIM;
    const __half* bptr = g_wprojh + ((size_t)e * H_DIM + n0 + lrow) * FF_DIM;

    float acc[4][4][4];
#pragma unroll
    for (int i = 0; i < 4; i++)
#pragma unroll
        for (int j = 0; j < 4; j++)
#pragma unroll
            for (int q = 0; q < 4; q++) acc[i][j][q] = 0.f;

    MAINLOOP(FF_DIM / 64);

    int ml = lane >> 2;
    int cl = (lane & 3) * 2;
#pragma unroll
    for (int i = 0; i < 4; i++) {
        int r0 = m0 + wm + 16 * i + ml;
        int r1 = r0 + 8;
#pragma unroll
        for (int j = 0; j < 4; j++) {
            int col = n0 + wn + 8 * j + cl;
            if (r0 < cnt) {
                float2 v = make_float2(acc[i][j][0], acc[i][j][1]);
                *(float2*)&g_pout[((size_t)e * T_TOK + r0) * H_DIM + col] = v;
            }
            if (r1 < cnt) {
                float2 v = make_float2(acc[i][j][2], acc[i][j][3]);
                *(float2*)&g_pout[((size_t)e * T_TOK + r1) * H_DIM + col] = v;
            }
        }
    }
}

// ---------------- combine ----------------
__global__ __launch_bounds__(256) void combine_kernel(float* __restrict__ out)
{
    int i = blockIdx.x * 256 + threadIdx.x;
    int t = i / (H_DIM / 4);
    int h4 = i - t * (H_DIM / 4);
    float g0 = g_gate[t * 2 + 0], g1 = g_gate[t * 2 + 1];
    int l0 = g_loc[t * 2 + 0], l1 = g_loc[t * 2 + 1];
    float4 a = *(const float4*)&g_pout[(size_t)l0 * H_DIM + h4 * 4];
    float4 b = *(const float4*)&g_pout[(size_t)l1 * H_DIM + h4 * 4];
    float4 r;
    r.x = g0 * a.x + g1 * b.x;
    r.y = g0 * a.y + g1 * b.y;
    r.z = g0 * a.z + g1 * b.z;
    r.w = g0 * a.w + g1 * b.w;
    *(float4*)&out[(size_t)t * H_DIM + h4 * 4] = r;
}

// ---------------- launch ----------------
extern "C" void kernel_launch(void* const* d_in, const int* in_sizes, int n_in,
                              void* d_out, int out_size)
{
    const float* x     = (const float*)d_in[0];
    const float* gw    = (const float*)d_in[1];
    const float* wfc   = (const float*)d_in[2];
    const float* wproj = (const float*)d_in[3];
    float* out    = (float*)d_out;
    float* logits = (float*)d_out + (size_t)T_TOK * H_DIM;

    cudaFuncSetAttribute(moe_gemm1_kernel, cudaFuncAttributeMaxDynamicSharedMemorySize, SMEM_BYTES);
    cudaFuncSetAttribute(moe_gemm2_kernel, cudaFuncAttributeMaxDynamicSharedMemorySize, SMEM_BYTES);

    __half* xh;     cudaGetSymbolAddress((void**)&xh, g_xh);
    __half* wfch;   cudaGetSymbolAddress((void**)&wfch, g_wfch);
    __half* wprojh; cudaGetSymbolAddress((void**)&wprojh, g_wprojh);

    init_kernel<<<1, 32>>>();
    gate_kernel<<<T_TOK / 8, 256>>>(x, gw, logits);

    cvt_fp16_kernel<<<(T_TOK * H_DIM / 8) / 256, 256>>>((const float4*)x, (uint4*)xh);
    cvt_fp16_kernel<<<((size_t)E_NUM * FF_DIM * H_DIM / 8) / 256, 256>>>((const float4*)wfc, (uint4*)wfch);
    cvt_fp16_kernel<<<((size_t)E_NUM * H_DIM * FF_DIM / 8) / 256, 256>>>((const float4*)wproj, (uint4*)wprojh);

    dim3 g1(FF_DIM / 128, T_TOK / 128, E_NUM);
    moe_gemm1_kernel<<<g1, 256, SMEM_BYTES>>>();
    dim3 g2(H_DIM / 128, T_TOK / 128, E_NUM);
    moe_gemm2_kernel<<<g2, 256, SMEM_BYTES>>>();

    combine_kernel<<<(T_TOK * H_DIM / 4) / 256, 256>>>(out);
}